// round 4
// baseline (speedup 1.0000x reference)
#include <cuda_runtime.h>

// LIF scan: mem = 0.25*mem + x[t]; spk = (mem >= 1.0); mem -= spk.
// Shape [T=100, 32, 16384] fp32. Sequential only in T; 524288 independent
// neuron lanes. One thread owns 2 neurons (float2) -> 262144 threads ->
// 1024 CTAs x 256: ~86% theoretical occupancy and 7-vs-6 CTA/SM balance
// (vs 4-vs-3 at float4/512 CTAs). Streaming cache hints: pure one-pass
// stream, no reuse.

#define T_STEPS 100
#define NEURONS (32 * 16384)          // 524288
#define VEC2    (NEURONS / 2)         // 262144 float2 lanes per timestep

__global__ __launch_bounds__(256) void lif_kernel(const float2* __restrict__ x,
                                                  float2* __restrict__ out) {
    const int i = blockIdx.x * blockDim.x + threadIdx.x;  // 0..VEC2-1

    float mx = 0.f, my = 0.f;

    const float2* __restrict__ xp = x + i;
    float2* __restrict__ op = out + i;

#pragma unroll 4
    for (int t = 0; t < T_STEPS; ++t) {
        const float2 xt = __ldcs(&xp[(long)t * VEC2]);

        mx = fmaf(0.25f, mx, xt.x);
        my = fmaf(0.25f, my, xt.y);

        const float sx = (mx >= 1.0f) ? 1.0f : 0.0f;
        const float sy = (my >= 1.0f) ? 1.0f : 0.0f;

        mx -= sx;
        my -= sy;

        float2 s;
        s.x = sx; s.y = sy;
        __stcs(&op[(long)t * VEC2], s);
    }
}

extern "C" void kernel_launch(void* const* d_in, const int* in_sizes, int n_in,
                              void* d_out, int out_size) {
    const float2* x = (const float2*)d_in[0];
    float2* out = (float2*)d_out;

    const int threads = 256;
    const int blocks = VEC2 / threads;  // 1024
    lif_kernel<<<blocks, threads>>>(x, out);
}

// round 8
// speedup vs baseline: 1.0346x; 1.0346x over previous
#include <cuda_runtime.h>

// LIF scan: mem = 0.25*mem + x[t]; spk = (mem >= 1.0); mem -= spk.
// Shape [T=100, 32, 16384] fp32. One thread owns 4 neurons (float4).
// Key change vs best-so-far: batch 10 timesteps per iteration —
// 10x LDG.128 issued back-to-back (160B in flight per warp, ~2.5x more
// latency-hiding than unroll-4), then compute, then 10x STG.128.
// Grouped same-direction bursts also cut DRAM R/W turnaround.

#define T_STEPS 100
#define UNROLL  10
#define NEURONS (32 * 16384)          // 524288
#define VEC4    (NEURONS / 4)         // 131072 float4 lanes per timestep

__global__ __launch_bounds__(256) void lif_kernel(const float4* __restrict__ x,
                                                  float4* __restrict__ out) {
    const int i = blockIdx.x * blockDim.x + threadIdx.x;  // 0..VEC4-1

    float mx = 0.f, my = 0.f, mz = 0.f, mw = 0.f;

    const float4* __restrict__ xp = x + i;
    float4* __restrict__ op = out + i;

    for (int tb = 0; tb < T_STEPS / UNROLL; ++tb) {
        float4 v[UNROLL];

        // Batch all loads: 10 independent LDG.128 in flight.
#pragma unroll
        for (int u = 0; u < UNROLL; ++u)
            v[u] = __ldcs(&xp[(long)(tb * UNROLL + u) * VEC4]);

        // Serial LIF recurrence over the 10 staged timesteps (in regs).
#pragma unroll
        for (int u = 0; u < UNROLL; ++u) {
            mx = fmaf(0.25f, mx, v[u].x);
            my = fmaf(0.25f, my, v[u].y);
            mz = fmaf(0.25f, mz, v[u].z);
            mw = fmaf(0.25f, mw, v[u].w);

            const float sx = (mx >= 1.0f) ? 1.0f : 0.0f;
            const float sy = (my >= 1.0f) ? 1.0f : 0.0f;
            const float sz = (mz >= 1.0f) ? 1.0f : 0.0f;
            const float sw = (mw >= 1.0f) ? 1.0f : 0.0f;

            mx -= sx;
            my -= sy;
            mz -= sz;
            mw -= sw;

            v[u].x = sx; v[u].y = sy; v[u].z = sz; v[u].w = sw;
        }

        // Batch all stores: 10 STG.128 back-to-back.
#pragma unroll
        for (int u = 0; u < UNROLL; ++u)
            __stcs(&op[(long)(tb * UNROLL + u) * VEC4], v[u]);
    }
}

extern "C" void kernel_launch(void* const* d_in, const int* in_sizes, int n_in,
                              void* d_out, int out_size) {
    const float4* x = (const float4*)d_in[0];
    float4* out = (float4*)d_out;

    const int threads = 256;
    const int blocks = VEC4 / threads;  // 512
    lif_kernel<<<blocks, threads>>>(x, out);
}

// round 10
// speedup vs baseline: 1.0537x; 1.0185x over previous
#include <cuda_runtime.h>

// LIF scan: mem = 0.25*mem + x[t]; spk = (mem >= 1.0); mem -= spk.
// Shape [T=100, 32, 16384] fp32. One thread owns 4 neurons (float4),
// accumulator in registers, coalesced streaming loads/stores per timestep.
//
// vs R3 (best, 512x256): identical per-warp code, but block=128/grid=1024.
// 512/148 = 3.46 CTAs/SM -> 68 SMs run 4 CTAs, 80 run 3 => ~15% tail where
// half the chip idles (explains DRAM stuck at 75%). 1024/148 = 6.92 ->
// 7-vs-6 CTAs/SM => 1.2% imbalance. Same resident warps, same bytes in
// flight per warp, just finer wave quantization.

#define T_STEPS 100
#define NEURONS (32 * 16384)          // 524288
#define VEC4    (NEURONS / 4)         // 131072 float4 lanes per timestep

__global__ __launch_bounds__(128) void lif_kernel(const float4* __restrict__ x,
                                                  float4* __restrict__ out) {
    const int i = blockIdx.x * blockDim.x + threadIdx.x;  // 0..VEC4-1

    float mx = 0.f, my = 0.f, mz = 0.f, mw = 0.f;

    const float4* __restrict__ xp = x + i;
    float4* __restrict__ op = out + i;

#pragma unroll 4
    for (int t = 0; t < T_STEPS; ++t) {
        const float4 xt = xp[(long)t * VEC4];

        mx = fmaf(0.25f, mx, xt.x);
        my = fmaf(0.25f, my, xt.y);
        mz = fmaf(0.25f, mz, xt.z);
        mw = fmaf(0.25f, mw, xt.w);

        const float sx = (mx >= 1.0f) ? 1.0f : 0.0f;
        const float sy = (my >= 1.0f) ? 1.0f : 0.0f;
        const float sz = (mz >= 1.0f) ? 1.0f : 0.0f;
        const float sw = (mw >= 1.0f) ? 1.0f : 0.0f;

        mx -= sx;
        my -= sy;
        mz -= sz;
        mw -= sw;

        float4 s;
        s.x = sx; s.y = sy; s.z = sz; s.w = sw;
        op[(long)t * VEC4] = s;
    }
}

extern "C" void kernel_launch(void* const* d_in, const int* in_sizes, int n_in,
                              void* d_out, int out_size) {
    const float4* x = (const float4*)d_in[0];
    float4* out = (float4*)d_out;

    const int threads = 128;
    const int blocks = VEC4 / threads;  // 1024
    lif_kernel<<<blocks, threads>>>(x, out);
}

// round 13
// speedup vs baseline: 1.1275x; 1.0700x over previous
#include <cuda_runtime.h>

// LIF scan: mem = 0.25*mem + x[t]; spk = (mem >= 1.0); mem -= spk.
// Shape [T=100, 32, 16384] fp32. One thread owns 4 neurons (float4),
// accumulator in registers, coalesced streaming loads/stores per timestep.
//
// vs R3 (best, unroll 4): #pragma unroll 2. Per B300 spread model,
// spr_max = 1.10 + max(0, 25*(oe*MLP_p1 - 16)/T_CTA); R3 sits exactly at
// the oe*MLP_p1 = 4*4 = 16 threshold for cross-CTA L1tex-queue contention
// (and R8's MLP_p1=10 regressed). MLP=2 still covers DRAM latency
// (~28KB in flight per SM vs ~14.5KB needed) while halving queue burst.

#define T_STEPS 100
#define NEURONS (32 * 16384)          // 524288
#define VEC4    (NEURONS / 4)         // 131072 float4 lanes per timestep

__global__ __launch_bounds__(256) void lif_kernel(const float4* __restrict__ x,
                                                  float4* __restrict__ out) {
    const int i = blockIdx.x * blockDim.x + threadIdx.x;  // 0..VEC4-1

    float mx = 0.f, my = 0.f, mz = 0.f, mw = 0.f;

    const float4* __restrict__ xp = x + i;
    float4* __restrict__ op = out + i;

#pragma unroll 2
    for (int t = 0; t < T_STEPS; ++t) {
        const float4 xt = xp[(long)t * VEC4];

        mx = fmaf(0.25f, mx, xt.x);
        my = fmaf(0.25f, my, xt.y);
        mz = fmaf(0.25f, mz, xt.z);
        mw = fmaf(0.25f, mw, xt.w);

        const float sx = (mx >= 1.0f) ? 1.0f : 0.0f;
        const float sy = (my >= 1.0f) ? 1.0f : 0.0f;
        const float sz = (mz >= 1.0f) ? 1.0f : 0.0f;
        const float sw = (mw >= 1.0f) ? 1.0f : 0.0f;

        mx -= sx;
        my -= sy;
        mz -= sz;
        mw -= sw;

        float4 s;
        s.x = sx; s.y = sy; s.z = sz; s.w = sw;
        op[(long)t * VEC4] = s;
    }
}

extern "C" void kernel_launch(void* const* d_in, const int* in_sizes, int n_in,
                              void* d_out, int out_size) {
    const float4* x = (const float4*)d_in[0];
    float4* out = (float4*)d_out;

    const int threads = 256;
    const int blocks = VEC4 / threads;  // 512
    lif_kernel<<<blocks, threads>>>(x, out);
}